// round 5
// baseline (speedup 1.0000x reference)
#include <cuda_runtime.h>

// Problem constants (fixed by dataset)
#define DD    128        // feature dim
#define KK2   256        // concat K = 2*D
#define NMAX  50048      // padded

// Scratch (device globals: allocations are forbidden)
__device__ float g_h0[NMAX * DD];      // layer-0 features (gathered emb)
__device__ float g_h1[NMAX * DD];      // layer-1 output (post relu)
__device__ float g_neigh1[NMAX * DD];  // scatter accumulator, layer 1
__device__ float g_neigh2[NMAX * DD];  // scatter accumulator, layer 2
__device__ float g_deg[NMAX];
// Pre-split tf32 weights: Bcat[k][j] = k<128 ? Ws[j][k] : Wn[j][k-128]
__device__ unsigned g_Bh[2][KK2 * DD];   // tf32 hi
__device__ unsigned g_Bl[2][KK2 * DD];   // tf32 lo (residual)

__device__ __forceinline__ unsigned f2tf(float x)
{
    unsigned r;
    asm("cvt.rna.tf32.f32 %0, %1;" : "=r"(r) : "f"(x));
    return r;
}

// ---------------------------------------------------------------------------
// h0 = emb[node_ids]; zero both neigh accumulators and degree
// ---------------------------------------------------------------------------
__global__ void k_init(const int* __restrict__ node_ids,
                       const float* __restrict__ emb, int N)
{
    int total = N * DD;
    for (int i = blockIdx.x * blockDim.x + threadIdx.x; i < total;
         i += gridDim.x * blockDim.x) {
        int n = i >> 7;
        int k = i & 127;
        g_h0[i]     = emb[(size_t)node_ids[n] * DD + k];
        g_neigh1[i] = 0.0f;
        g_neigh2[i] = 0.0f;
        if (i < N) g_deg[i] = 0.0f;
    }
}

// ---------------------------------------------------------------------------
// Pre-split Bcat into tf32 hi/lo for both layers
// ---------------------------------------------------------------------------
__global__ void k_transB(const float* __restrict__ Ws1, const float* __restrict__ Wn1,
                         const float* __restrict__ Ws2, const float* __restrict__ Wn2)
{
    int i = blockIdx.x * blockDim.x + threadIdx.x;   // 2 * 256 * 128
    if (i >= 2 * KK2 * DD) return;
    int l = i >> 15;
    int r = i & 32767;
    int k = r >> 7;
    int j = r & 127;
    const float* Ws = l ? Ws2 : Ws1;
    const float* Wn = l ? Wn2 : Wn1;
    float v = (k < DD) ? Ws[j * DD + k] : Wn[j * DD + (k - DD)];
    unsigned hi = f2tf(v);
    unsigned lo = f2tf(v - __uint_as_float(hi));
    g_Bh[l][r] = hi;
    g_Bl[l][r] = lo;
}

// ---------------------------------------------------------------------------
// Scatter: one warp per edge. neigh[dst] += w * h[src] via RED.128
// ---------------------------------------------------------------------------
__global__ void k_scatter(const float* __restrict__ h,
                          const int* __restrict__ src,
                          const int* __restrict__ dst,
                          const float* __restrict__ w,
                          float* __restrict__ neigh,
                          int E, int count_deg)
{
    int gw   = (blockIdx.x * blockDim.x + threadIdx.x) >> 5;
    int lane = threadIdx.x & 31;
    if (gw >= E) return;

    int   s  = src[gw];
    int   t  = dst[gw];
    float we = w[gw];

    if (count_deg && lane == 0) atomicAdd(&g_deg[t], 1.0f);

    float4 v = *reinterpret_cast<const float4*>(h + (size_t)s * DD + lane * 4);
    v.x *= we; v.y *= we; v.z *= we; v.w *= we;
    float* p = neigh + (size_t)t * DD + lane * 4;
#if defined(__CUDA_ARCH__) && __CUDA_ARCH__ >= 900
    atomicAdd(reinterpret_cast<float4*>(p), v);
#else
    atomicAdd(p + 0, v.x); atomicAdd(p + 1, v.y);
    atomicAdd(p + 2, v.z); atomicAdd(p + 3, v.w);
#endif
}

// ---------------------------------------------------------------------------
// Tensor-core GEMM (3xTF32, pre-split operands):
//   out[M x 128] = [h | neigh/deg][M x 256] @ Bcat + bias
// 128x128 tile, BK=16, 8 warps (4m x 2n), warp tile 32m x 64n.
// Smem holds tf32 hi/lo for A and B -> inner loop is LDS + HMMA only.
// AP=20: frag bank = (20g+t)%32 all-distinct. BP=136: (8t+g)%32 all-distinct.
// ---------------------------------------------------------------------------
#define BKC 16
#define AP  20
#define BP  136

__device__ __forceinline__ void mma8(float* d, const unsigned* a, const unsigned* b)
{
    asm volatile(
        "mma.sync.aligned.m16n8k8.row.col.f32.tf32.tf32.f32 "
        "{%0,%1,%2,%3}, {%4,%5,%6,%7}, {%8,%9}, {%0,%1,%2,%3};"
        : "+f"(d[0]), "+f"(d[1]), "+f"(d[2]), "+f"(d[3])
        : "r"(a[0]), "r"(a[1]), "r"(a[2]), "r"(a[3]), "r"(b[0]), "r"(b[1]));
}

__global__ void __launch_bounds__(256)
k_gemm(const float* __restrict__ hmat, const float* __restrict__ nmat,
       const unsigned* __restrict__ Bhg, const unsigned* __restrict__ Blg,
       const float* __restrict__ bias,
       float* __restrict__ out, int M, int do_relu)
{
    __shared__ unsigned Ah[128 * AP];   // [m][k] pitch 20
    __shared__ unsigned Al[128 * AP];
    __shared__ unsigned Bh[BKC * BP];   // [k][n] pitch 136
    __shared__ unsigned Bl[BKC * BP];

    int tid  = threadIdx.x;
    int m0   = blockIdx.x * 128;
    int wid  = tid >> 5;
    int lane = tid & 31;
    int wm   = wid & 3;              // rows wm*32..+31
    int wn   = wid >> 2;             // cols wn*64..+63
    int g    = lane >> 2;
    int t    = lane & 3;

    // A-loader rows (2 slots) and their 1/max(deg,1)
    float invd[2];
#pragma unroll
    for (int s = 0; s < 2; ++s) {
        int row = m0 + (tid >> 2) + 64 * s;
        float d = (row < M) ? g_deg[row] : 1.0f;
        invd[s] = 1.0f / fmaxf(d, 1.0f);
    }

    float acc[2][8][4];
#pragma unroll
    for (int mt = 0; mt < 2; ++mt)
#pragma unroll
        for (int nt = 0; nt < 8; ++nt)
#pragma unroll
            for (int v = 0; v < 4; ++v) acc[mt][nt][v] = 0.0f;

    // Loaders: A slot s -> row m=(tid>>2)+64s, 4 k at 4*(tid&3); convert to hi/lo.
    auto ldgA = [&](int c, int s, uint4& hi, uint4& lo) {
        int m   = (tid >> 2) + 64 * s;
        int gk  = c * BKC + 4 * (tid & 3);
        int row = m0 + m;
        float4 v;
        if (row >= M) v = make_float4(0.f, 0.f, 0.f, 0.f);
        else if (gk < DD)
            v = *reinterpret_cast<const float4*>(hmat + (size_t)row * DD + gk);
        else {
            v = *reinterpret_cast<const float4*>(nmat + (size_t)row * DD + gk - DD);
            float iv = invd[s];
            v.x *= iv; v.y *= iv; v.z *= iv; v.w *= iv;
        }
        hi.x = f2tf(v.x); lo.x = f2tf(v.x - __uint_as_float(hi.x));
        hi.y = f2tf(v.y); lo.y = f2tf(v.y - __uint_as_float(hi.y));
        hi.z = f2tf(v.z); lo.z = f2tf(v.z - __uint_as_float(hi.z));
        hi.w = f2tf(v.w); lo.w = f2tf(v.w - __uint_as_float(hi.w));
    };
    auto stA = [&](int s, uint4 hi, uint4 lo) {
        int m    = (tid >> 2) + 64 * s;
        int base = m * AP + 4 * (tid & 3);
        *reinterpret_cast<uint4*>(&Ah[base]) = hi;
        *reinterpret_cast<uint4*>(&Al[base]) = lo;
    };
    // B slot s -> k=(fidx>>5), 4 n at 4*(fidx&31); pre-split in global.
    auto ldgB = [&](int c, int s, uint4& hi, uint4& lo) {
        int fidx = tid + s * 256;
        int k    = fidx >> 5;
        int nq   = fidx & 31;
        size_t off = (size_t)(c * BKC + k) * DD + 4 * nq;
        hi = *reinterpret_cast<const uint4*>(Bhg + off);
        lo = *reinterpret_cast<const uint4*>(Blg + off);
    };
    auto stB = [&](int s, uint4 hi, uint4 lo) {
        int fidx = tid + s * 256;
        int base = (fidx >> 5) * BP + 4 * (fidx & 31);
        *reinterpret_cast<uint4*>(&Bh[base]) = hi;
        *reinterpret_cast<uint4*>(&Bl[base]) = lo;
    };

    uint4 rah[2], ral[2], rbh[2], rbl[2];
#pragma unroll
    for (int s = 0; s < 2; ++s) {
        ldgA(0, s, rah[s], ral[s]);
        ldgB(0, s, rbh[s], rbl[s]);
    }

    const int NC = KK2 / BKC;   // 16 chunks
    for (int c = 0; c < NC; ++c) {
        __syncthreads();        // previous compute done, smem reusable
#pragma unroll
        for (int s = 0; s < 2; ++s) { stA(s, rah[s], ral[s]); stB(s, rbh[s], rbl[s]); }
        __syncthreads();
        if (c < NC - 1) {
#pragma unroll
            for (int s = 0; s < 2; ++s) {
                ldgA(c + 1, s, rah[s], ral[s]);
                ldgB(c + 1, s, rbh[s], rbl[s]);
            }
        }

#pragma unroll
        for (int kk = 0; kk < BKC / 8; ++kk) {
            int kc = kk * 8;
            unsigned ahi[2][4], alo[2][4];
#pragma unroll
            for (int mt = 0; mt < 2; ++mt) {
                int rm = wm * 32 + mt * 16;
                ahi[mt][0] = Ah[(rm + g) * AP + kc + t];
                ahi[mt][1] = Ah[(rm + g + 8) * AP + kc + t];
                ahi[mt][2] = Ah[(rm + g) * AP + kc + t + 4];
                ahi[mt][3] = Ah[(rm + g + 8) * AP + kc + t + 4];
                alo[mt][0] = Al[(rm + g) * AP + kc + t];
                alo[mt][1] = Al[(rm + g + 8) * AP + kc + t];
                alo[mt][2] = Al[(rm + g) * AP + kc + t + 4];
                alo[mt][3] = Al[(rm + g + 8) * AP + kc + t + 4];
            }
#pragma unroll
            for (int nt = 0; nt < 8; ++nt) {
                int cn = wn * 64 + nt * 8 + g;
                unsigned bhi[2], blo[2];
                bhi[0] = Bh[(kc + t) * BP + cn];
                bhi[1] = Bh[(kc + t + 4) * BP + cn];
                blo[0] = Bl[(kc + t) * BP + cn];
                blo[1] = Bl[(kc + t + 4) * BP + cn];
#pragma unroll
                for (int mt = 0; mt < 2; ++mt) {
                    mma8(acc[mt][nt], ahi[mt], bhi);
                    mma8(acc[mt][nt], ahi[mt], blo);
                    mma8(acc[mt][nt], alo[mt], bhi);
                }
            }
        }
    }

    // Epilogue: bias (+relu), float2 stores
#pragma unroll
    for (int nt = 0; nt < 8; ++nt) {
        int col = wn * 64 + nt * 8 + 2 * t;
        float bx = bias[col], by = bias[col + 1];
#pragma unroll
        for (int mt = 0; mt < 2; ++mt) {
#pragma unroll
            for (int half = 0; half < 2; ++half) {
                int row = m0 + wm * 32 + mt * 16 + g + 8 * half;
                if (row < M) {
                    float vx = acc[mt][nt][2 * half + 0] + bx;
                    float vy = acc[mt][nt][2 * half + 1] + by;
                    if (do_relu) { vx = fmaxf(vx, 0.f); vy = fmaxf(vy, 0.f); }
                    *reinterpret_cast<float2*>(out + (size_t)row * DD + col)
                        = make_float2(vx, vy);
                }
            }
        }
    }
}

// ---------------------------------------------------------------------------
// init -> transB -> scatter1 -> gemm1 -> scatter2 -> gemm2
// Inputs: node_ids, edge_src, edge_dst, edge_weight, emb,
//         W_self1, W_neigh1, b1, W_self2, W_neigh2, b2
// ---------------------------------------------------------------------------
extern "C" void kernel_launch(void* const* d_in, const int* in_sizes, int n_in,
                              void* d_out, int out_size)
{
    const int*   node_ids = (const int*)  d_in[0];
    const int*   esrc     = (const int*)  d_in[1];
    const int*   edst     = (const int*)  d_in[2];
    const float* ew       = (const float*)d_in[3];
    const float* emb      = (const float*)d_in[4];
    const float* Ws1      = (const float*)d_in[5];
    const float* Wn1      = (const float*)d_in[6];
    const float* b1       = (const float*)d_in[7];
    const float* Ws2      = (const float*)d_in[8];
    const float* Wn2      = (const float*)d_in[9];
    const float* b2       = (const float*)d_in[10];

    int N = in_sizes[0];
    int E = in_sizes[1];
    float* out = (float*)d_out;

    void *p_h0_v, *p_h1_v, *p_n1_v, *p_n2_v, *p_Bh_v, *p_Bl_v;
    cudaGetSymbolAddress(&p_h0_v, g_h0);
    cudaGetSymbolAddress(&p_h1_v, g_h1);
    cudaGetSymbolAddress(&p_n1_v, g_neigh1);
    cudaGetSymbolAddress(&p_n2_v, g_neigh2);
    cudaGetSymbolAddress(&p_Bh_v, g_Bh);
    cudaGetSymbolAddress(&p_Bl_v, g_Bl);
    const float* p_h0 = (const float*)p_h0_v;
    const float* p_h1 = (const float*)p_h1_v;
    const float* p_n1 = (const float*)p_n1_v;
    const float* p_n2 = (const float*)p_n2_v;
    const unsigned* p_Bh = (const unsigned*)p_Bh_v;
    const unsigned* p_Bl = (const unsigned*)p_Bl_v;

    const int TB = 256;
    int sblocks = (E + 7) / 8;
    int gblocks = (N + 127) / 128;

    k_init<<<2048, TB>>>(node_ids, emb, N);
    k_transB<<<(2 * KK2 * DD + TB - 1) / TB, TB>>>(Ws1, Wn1, Ws2, Wn2);

    // Layer 1
    k_scatter<<<sblocks, TB>>>(p_h0, esrc, edst, ew, (float*)p_n1_v, E, 1);
    k_gemm<<<gblocks, TB>>>(p_h0, p_n1, p_Bh, p_Bl, b1, (float*)p_h1_v, N, 1);

    // Layer 2
    k_scatter<<<sblocks, TB>>>(p_h1, esrc, edst, ew, (float*)p_n2_v, E, 0);
    k_gemm<<<gblocks, TB>>>(p_h1, p_n2, p_Bh + KK2 * DD, p_Bl + KK2 * DD,
                            b2, out, N, 0);
}